// round 11
// baseline (speedup 1.0000x reference)
#include <cuda_runtime.h>

// out[i] = { cos(x0), cos(x0)cos(x1), cos(x0)cos(x1)cos(x2), cos(x0)..cos(x3) }
// (circuit collapses analytically; weights are irrelevant — see R1 derivation)
//
// R9: converged config — restore R3 (measured best of the full shape sweep):
// VPT=2, 256 threads, grid=1024 (single wave, ~7 blocks/SM all resident),
// MLP_p1=2 front-batched LDG.128, MUFU __cosf. Remaining time is launch-ramp
// + memory-latency floor (~T_ovh 5000 cyc + 2700 cyc LTS traffic), not
// addressable in-kernel; perfect-wave grid=1184 variant has identical max
// per-SM work (3584 rows) so placement offers no further win.

constexpr int VPT = 2;          // rows (float4) per thread
constexpr int THREADS = 256;

__global__ __launch_bounds__(THREADS, 8) void qlg_kernel(const float4* __restrict__ x,
                                                         float4* __restrict__ out) {
    int base = blockIdx.x * (THREADS * VPT) + threadIdx.x;

    float4 v[VPT];
#pragma unroll
    for (int j = 0; j < VPT; j++) {
        v[j] = x[base + j * THREADS];       // front-batched, coalesced
    }

#pragma unroll
    for (int j = 0; j < VPT; j++) {
        float c0 = __cosf(v[j].x);
        float c1 = c0 * __cosf(v[j].y);
        float c2 = c1 * __cosf(v[j].z);
        float c3 = c2 * __cosf(v[j].w);
        out[base + j * THREADS] = make_float4(c0, c1, c2, c3);
    }
}

extern "C" void kernel_launch(void* const* d_in, const int* in_sizes, int n_in,
                              void* d_out, int out_size) {
    const float4* x = (const float4*)d_in[0];   // [B,4] float32
    float4* out = (float4*)d_out;               // [B,4] float32
    int n_rows = in_sizes[0] / 4;               // B = 524288 (divisible by 512)
    int blocks = n_rows / (THREADS * VPT);      // 1024 — single wave
    qlg_kernel<<<blocks, THREADS>>>(x, out);
}

// round 12
// speedup vs baseline: 1.1822x; 1.1822x over previous
#include <cuda_runtime.h>

// out[i] = { cos(x0), cos(x0)cos(x1), cos(x0)cos(x1)cos(x2), cos(x0)..cos(x3) }
// (circuit collapses analytically; weights are irrelevant — see R1 derivation)
//
// R10 FINAL: converged config (R3, best measured 5.82us kernel / 6.62us harness).
// VPT=2, 256 threads, grid=1024 — the MINIMUM VPT giving single-wave residency
// (2048 thr/SM * 148 SM = 303104 < B = 524288 → VPT >= 1.73), MLP_p1=2
// front-batched LDG.128, MUFU __cosf. Shape sweep complete: VPT=1 (1.73 waves)
// 6.02us, VPT=4 (occupancy collapse) 7.62us, 128-thr rebalance neutral.
// Remaining time = launch ramp + latency drain floor; harness jitter (±1us)
// now exceeds all in-kernel deltas.

constexpr int VPT = 2;          // rows (float4) per thread
constexpr int THREADS = 256;

__global__ __launch_bounds__(THREADS) void qlg_kernel(const float4* __restrict__ x,
                                                      float4* __restrict__ out) {
    int base = blockIdx.x * (THREADS * VPT) + threadIdx.x;

    float4 v[VPT];
#pragma unroll
    for (int j = 0; j < VPT; j++) {
        v[j] = x[base + j * THREADS];       // front-batched, coalesced
    }

#pragma unroll
    for (int j = 0; j < VPT; j++) {
        float c0 = __cosf(v[j].x);
        float c1 = c0 * __cosf(v[j].y);
        float c2 = c1 * __cosf(v[j].z);
        float c3 = c2 * __cosf(v[j].w);
        out[base + j * THREADS] = make_float4(c0, c1, c2, c3);
    }
}

extern "C" void kernel_launch(void* const* d_in, const int* in_sizes, int n_in,
                              void* d_out, int out_size) {
    const float4* x = (const float4*)d_in[0];   // [B,4] float32
    float4* out = (float4*)d_out;               // [B,4] float32
    int n_rows = in_sizes[0] / 4;               // B = 524288 (divisible by 512)
    int blocks = n_rows / (THREADS * VPT);      // 1024 — single wave
    qlg_kernel<<<blocks, THREADS>>>(x, out);
}